// round 15
// baseline (speedup 1.0000x reference)
#include <cuda_runtime.h>
#include <math_constants.h>
#include <cstdint>

#define NN   768
#define IN   68
#define KNB  8
#define EO   32
#define FEAT 264
#define XW   132
#define EMB  32
#define MPAIR 294528
#define EPS  1e-5f
#define TILES_PER_G 312   // 48 a-tiles(16 rows) x pruned 64-col b-tiles

// ---------------- scratch (device globals, no allocation) ----------------
__device__ int   g_idx[2][NN][KNB];
__device__ float g_e1[2][NN][EO];
__device__ float g_x[2][NN][XW];
__device__ float g_accum[4][XW];
__device__ __align__(16) float g_A[2][NN][EMB];
__device__ __align__(16) float g_B[2][NN][EMB];

__device__ __forceinline__ float lrelu(float x) { return fmaxf(x, 0.01f * x); }

// ---- packed f32x2 helpers ----
__device__ __forceinline__ unsigned long long pk2(float lo, float hi) {
    unsigned long long r;
    asm("mov.b64 %0, {%1,%2};" : "=l"(r) : "f"(lo), "f"(hi));
    return r;
}
__device__ __forceinline__ void upk2(float& lo, float& hi, unsigned long long p) {
    asm("mov.b64 {%0,%1}, %2;" : "=f"(lo), "=f"(hi) : "l"(p));
}
__device__ __forceinline__ unsigned long long fma2(unsigned long long a,
                                                   unsigned long long b,
                                                   unsigned long long c) {
    unsigned long long d;
    asm("fma.rn.f32x2 %0, %1, %2, %3;" : "=l"(d) : "l"(a), "l"(b), "l"(c));
    return d;
}
__device__ __forceinline__ unsigned long long mul2(unsigned long long a,
                                                   unsigned long long b) {
    unsigned long long d;
    asm("mul.rn.f32x2 %0, %1, %2;" : "=l"(d) : "l"(a), "l"(b));
    return d;
}
__device__ __forceinline__ unsigned long long lrelu2(unsigned long long x,
                                                     unsigned long long c1,
                                                     unsigned long long c2) {
    unsigned long long ax = x & 0x7FFFFFFF7FFFFFFFull;
    return fma2(x, c1, mul2(ax, c2));
}

// ======== 1) fused KNN + EdgeConv1: 4 nodes/block (1 per warp) ========
__global__ void __launch_bounds__(128) knn_ec1_kernel(
        const float* __restrict__ feat0, const float* __restrict__ feat1,
        const float* __restrict__ w1, const float* __restrict__ b1,
        const float* __restrict__ w2, const float* __restrict__ b2) {
    __shared__ __align__(16) unsigned char smem_u[NN * 16];
    __shared__ float s1[4][EO];
    __shared__ int   sidx[4][KNB];

    int g = blockIdx.y;
    int tid = threadIdx.x, wid = tid >> 5, lane = tid & 31;
    const float* feat = g ? feat1 : feat0;
    int node = blockIdx.x * 4 + wid;

    if (blockIdx.x == 0 && g == 0) {
        float* acc = (float*)g_accum;
        for (int t = tid; t < 4 * XW; t += 128) acc[t] = 0.f;
    }

    float4* sc = (float4*)smem_u;
    for (int t = tid; t < NN; t += 128)
        sc[t] = *(const float4*)(feat + t * IN);
    __syncthreads();

    {
        float4 ci = sc[node];
        float dloc[NN / 32];
#pragma unroll
        for (int t = 0; t < NN / 32; t++) {
            float4 cj = sc[lane + t * 32];
            dloc[t] = fabsf(ci.x - cj.x) + fabsf(ci.y - cj.y) +
                      fabsf(ci.z - cj.z) + fabsf(ci.w - cj.w);
        }
        for (int r = 0; r < KNB; r++) {
            float best = CUDART_INF_F;
            int bt = 0;
#pragma unroll
            for (int t = 0; t < NN / 32; t++)
                if (dloc[t] < best) { best = dloc[t]; bt = t; }
            int bj = lane + bt * 32;
            unsigned long long key =
                (((unsigned long long)__float_as_uint(best)) << 32) | (unsigned)bj;
#pragma unroll
            for (int off = 16; off; off >>= 1) {
                unsigned long long other = __shfl_xor_sync(0xffffffffu, key, off);
                if (other < key) key = other;
            }
            int wj = (int)(key & 0xffffffffu);
            if (lane == (wj & 31)) dloc[wj >> 5] = CUDART_INF_F;
            if (lane == 0) {
                sidx[wid][r] = wj;
                g_idx[g][node][r] = wj;
            }
        }
    }
    __syncthreads();

    float (*sh)[KNB][IN] = (float (*)[KNB][IN])smem_u;
    for (int t = lane; t < KNB * IN; t += 32) {
        int k = t / IN, f = t - k * IN;
        sh[wid][k][f] = feat[sidx[wid][k] * IN + f];
    }
    __syncwarp();

    float p0 = b1[lane], p1 = 0.f;
    const float (*sa)[IN] = sh[wid];
    for (int f = 0; f < IN; f += 2) {
#pragma unroll
        for (int k = 0; k < KNB; k++) {
            p0 = fmaf(sa[k][f],     w1[(f * KNB + k) * EO + lane],       p0);
            p1 = fmaf(sa[k][f + 1], w1[((f + 1) * KNB + k) * EO + lane], p1);
        }
    }
    s1[wid][lane] = lrelu(p0 + p1);
    __syncwarp();

    float h = b2[lane];
#pragma unroll
    for (int k = 0; k < EO; k++)
        h = fmaf(s1[wid][k], w2[k * EO + lane], h);
    g_e1[g][node][lane] = lrelu(h);
}

// ------- 2) EdgeConv2 (smem weights) + assemble x + bn partials -------
__global__ void __launch_bounds__(128) ec2_kernel(
        const float* __restrict__ feat0, const float* __restrict__ feat1,
        const float* __restrict__ w1, const float* __restrict__ b1,
        const float* __restrict__ w2, const float* __restrict__ b2) {
    __shared__ float sw1[EO * KNB * EO];
    __shared__ float sw2[EO * EO];
    __shared__ float sh[4][KNB][EO];
    __shared__ float s1[4][EO];
    __shared__ float pacc[4][XW];
    int g = blockIdx.y;
    int tid = threadIdx.x;
    int wid = tid >> 5, lane = tid & 31;
    int node = blockIdx.x * 4 + wid;

    for (int t = tid; t < EO * KNB * EO / 4; t += 128)
        ((float4*)sw1)[t] = ((const float4*)w1)[t];
    for (int t = tid; t < EO * EO / 4; t += 128)
        ((float4*)sw2)[t] = ((const float4*)w2)[t];
    for (int t = tid; t < 4 * XW; t += 128) ((float*)pacc)[t] = 0.f;

    for (int t = lane; t < KNB * EO; t += 32) {
        int k = t >> 5, f = t & 31;
        sh[wid][k][f] = g_e1[g][g_idx[g][node][k]][f];
    }
    __syncthreads();

    float p0 = b1[lane], p1 = 0.f;
    const float (*sa)[EO] = sh[wid];
    for (int f = 0; f < EO; f += 2) {
#pragma unroll
        for (int k = 0; k < KNB; k++) {
            p0 = fmaf(sa[k][f],     sw1[(f * KNB + k) * EO + lane],       p0);
            p1 = fmaf(sa[k][f + 1], sw1[((f + 1) * KNB + k) * EO + lane], p1);
        }
    }
    s1[wid][lane] = lrelu(p0 + p1);
    __syncwarp();

    float h = b2[lane];
#pragma unroll
    for (int k = 0; k < EO; k++)
        h = fmaf(s1[wid][k], sw2[k * EO + lane], h);

    const float* feat = g ? feat1 : feat0;
    float* xp = g_x[g][node];
    for (int f = lane; f < IN; f += 32) xp[f] = feat[node * IN + f];
    xp[IN + lane]      = g_e1[g][node][lane];
    xp[IN + EO + lane] = lrelu(h);
    __syncthreads();

    {
        float wa = (float)(NN - 1 - node);
        float wb = (float)node;
        for (int f = lane; f < XW; f += 32) {
            float v = g_x[g][node][f];
            atomicAdd(&pacc[0][f], wa * v);
            atomicAdd(&pacc[1][f], wb * v);
            atomicAdd(&pacc[2][f], wa * v * v);
            atomicAdd(&pacc[3][f], wb * v * v);
        }
    }
    __syncthreads();
    for (int t = tid; t < 4 * XW; t += 128)
        atomicAdd(&((float*)g_accum)[t], ((float*)pacc)[t]);
}

// ------- 3) per-node A, B: smem lin1_w, block-shared be -------
__global__ void __launch_bounds__(128) ab_kernel(const float* __restrict__ lin1_w,
                                                 const float* __restrict__ lin1_b,
                                                 const float* __restrict__ bn_g,
                                                 const float* __restrict__ bn_b) {
    __shared__ float sw[FEAT * EMB];
    __shared__ float sscale[FEAT], sshift[FEAT];
    __shared__ float sbe[4][EMB];
    __shared__ float sx[4][XW];
    int g = blockIdx.y;
    int tid = threadIdx.x;
    int wid = tid >> 5, lane = tid & 31;
    int node = blockIdx.x * 4 + wid;

    for (int t = tid; t < FEAT * EMB / 4; t += 128)
        ((float4*)sw)[t] = ((const float4*)lin1_w)[t];
    for (int f = tid; f < XW; f += 128) {
        float inv = 1.0f / (2.0f * (float)MPAIR);
        float s1 = g_accum[0][f], s2 = g_accum[1][f];
        float q1 = g_accum[2][f], q2 = g_accum[3][f];
        float mu1 = s1 * inv, var1 = fmaf(-mu1, mu1, q1 * inv);
        float mu2 = s2 * inv, var2 = fmaf(-mu2, mu2, q2 * inv);
        float sc1 = bn_g[f]      * rsqrtf(var1 + EPS);
        float sc2 = bn_g[XW + f] * rsqrtf(var2 + EPS);
        sscale[f]      = sc1;
        sscale[XW + f] = sc2;
        sshift[f]      = bn_b[f]      - mu1 * sc1;
        sshift[XW + f] = bn_b[XW + f] - mu2 * sc2;
    }
    {
        const float* x = g_x[g][node];
        for (int f = lane; f < XW; f += 32) sx[wid][f] = x[f];
    }
    __syncthreads();

    {
        float p = 0.f;
        for (int ff = wid; ff < FEAT; ff += 4)
            p = fmaf(sshift[ff], sw[ff * EMB + lane], p);
        sbe[wid][lane] = p;
    }
    __syncthreads();

    float a = lin1_b[lane] + sbe[0][lane] + sbe[1][lane] + sbe[2][lane] + sbe[3][lane];
    float b = 0.f;
    for (int f = 0; f < XW; f++) {
        float xv = sx[wid][f];
        a = fmaf(xv * sscale[f],      sw[f * EMB + lane],        a);
        b = fmaf(xv * sscale[XW + f], sw[(XW + f) * EMB + lane], b);
    }
    g_A[g][node][lane] = a;
    g_B[g][node][lane] = b;
}

// ------- 4) pair kernel: 16i x 64j tiles, 4 pairs/thread, 256 threads -------
__global__ void __launch_bounds__(256) pair_kernel(
        const float* __restrict__ w2, const float* __restrict__ b2,
        const float* __restrict__ w3, const float* __restrict__ b3,
        float* __restrict__ out) {
    __shared__ float sA[16][33];
    __shared__ float sBT[EMB][68];
    __shared__ __align__(16) float sW2[EMB * EMB];
    __shared__ unsigned long long sW3a[16], sW3b[16], sB2[16];
    __shared__ float b3s[2];

    int tid = threadIdx.x;
    int gg = blockIdx.y;

    // decode tile -> (a, bcol): pruned 48 x 12 grid (only tiles with j-range > i-range start)
    int id = blockIdx.x, a = 0, bcol = 0;
    for (;;) {
        int bmin = (16 * a + 1) >> 6;
        int cnt = 12 - bmin;
        if (id < cnt) { bcol = bmin + id; break; }
        id -= cnt; a++;
    }
    int i0 = a * 16, j0 = bcol * 64;

    for (int t = tid; t < 256; t += 256)
        ((float4*)sW2)[t] = ((const float4*)w2)[t];
    if (tid < 16) {
        sB2[tid]  = ((const unsigned long long*)b2)[tid];
        sW3a[tid] = pk2(w3[4 * tid],     w3[4 * tid + 2]);
        sW3b[tid] = pk2(w3[4 * tid + 1], w3[4 * tid + 3]);
    }
    if (tid < 2) b3s[tid] = b3[tid];

    if (tid < 128) {
        float4 v = ((const float4*)g_A[gg][i0])[tid];
        int r = tid >> 3, c = (tid & 7) * 4;
        sA[r][c] = v.x; sA[r][c + 1] = v.y; sA[r][c + 2] = v.z; sA[r][c + 3] = v.w;
    }
    for (int q = tid; q < 512; q += 256) {
        float4 v = ((const float4*)g_B[gg][j0])[q];
        int r = q >> 3, c = (q & 7) * 4;
        sBT[c + 0][r] = v.x;
        sBT[c + 1][r] = v.y;
        sBT[c + 2][r] = v.z;
        sBT[c + 3][r] = v.w;
    }
    __syncthreads();

    const unsigned long long c1 = pk2(0.505f, 0.505f);
    const unsigned long long c2 = pk2(0.495f, 0.495f);
    const ulonglong2* wv = (const ulonglong2*)sW2;
    int ty = tid >> 4, tx = tid & 15;
    int i = i0 + ty, jb = j0 + 4 * tx;

    unsigned long long oa[4] = {0, 0, 0, 0}, ob[4] = {0, 0, 0, 0};

#pragma unroll
    for (int s = 0; s < 2; s++) {
        unsigned long long acc[4][8];
#pragma unroll
        for (int p = 0; p < 4; p++)
#pragma unroll
            for (int m = 0; m < 8; m++) acc[p][m] = sB2[8 * s + m];

#pragma unroll 8
        for (int k = 0; k < EMB; k++) {
            float av = sA[ty][k];
            float4 bv = *(const float4*)&sBT[k][4 * tx];
            float f0 = lrelu(av + bv.x), f1 = lrelu(av + bv.y);
            float f2 = lrelu(av + bv.z), f3 = lrelu(av + bv.w);
            unsigned long long h0 = pk2(f0, f0), h1 = pk2(f1, f1);
            unsigned long long h2 = pk2(f2, f2), h3 = pk2(f3, f3);
#pragma unroll
            for (int q2 = 0; q2 < 4; q2++) {
                ulonglong2 w = wv[k * 8 + 4 * s + q2];
                acc[0][2 * q2]     = fma2(h0, w.x, acc[0][2 * q2]);
                acc[0][2 * q2 + 1] = fma2(h0, w.y, acc[0][2 * q2 + 1]);
                acc[1][2 * q2]     = fma2(h1, w.x, acc[1][2 * q2]);
                acc[1][2 * q2 + 1] = fma2(h1, w.y, acc[1][2 * q2 + 1]);
                acc[2][2 * q2]     = fma2(h2, w.x, acc[2][2 * q2]);
                acc[2][2 * q2 + 1] = fma2(h2, w.y, acc[2][2 * q2 + 1]);
                acc[3][2 * q2]     = fma2(h3, w.x, acc[3][2 * q2]);
                acc[3][2 * q2 + 1] = fma2(h3, w.y, acc[3][2 * q2 + 1]);
            }
        }
#pragma unroll
        for (int m = 0; m < 8; m++) {
            int mg = 8 * s + m;
            unsigned long long wa = sW3a[mg], wb = sW3b[mg];
#pragma unroll
            for (int p = 0; p < 4; p++) {
                unsigned long long hh = lrelu2(acc[p][m], c1, c2);
                oa[p] = fma2(hh, wa, oa[p]);
                ob[p] = fma2(hh, wb, ob[p]);
            }
        }
    }

    long long obase = (long long)gg * MPAIR;
    int base = i * (2 * NN - 1 - i) / 2 - i - 1;
#pragma unroll
    for (int p = 0; p < 4; p++) {
        int j = jb + p;
        if (j > i) {
            float lo, hi;
            upk2(lo, hi, oa[p]); float r0 = lo + hi + b3s[0];
            upk2(lo, hi, ob[p]); float r1 = lo + hi + b3s[1];
            ((float2*)out)[obase + base + j] = make_float2(r0, r1);
        }
    }
}

// ---------------- launch ----------------
extern "C" void kernel_launch(void* const* d_in, const int* in_sizes, int n_in,
                              void* d_out, int out_size) {
    const float* feat0  = (const float*)d_in[0];
    const float* feat1  = (const float*)d_in[1];
    const float* ec1_w1 = (const float*)d_in[2];
    const float* ec1_b1 = (const float*)d_in[3];
    const float* ec1_w2 = (const float*)d_in[4];
    const float* ec1_b2 = (const float*)d_in[5];
    const float* ec2_w1 = (const float*)d_in[6];
    const float* ec2_b1 = (const float*)d_in[7];
    const float* ec2_w2 = (const float*)d_in[8];
    const float* ec2_b2 = (const float*)d_in[9];
    const float* bn_g   = (const float*)d_in[10];
    const float* bn_b   = (const float*)d_in[11];
    const float* lin1_w = (const float*)d_in[12];
    const float* lin1_b = (const float*)d_in[13];
    const float* lin2_w = (const float*)d_in[14];
    const float* lin2_b = (const float*)d_in[15];
    const float* lin3_w = (const float*)d_in[16];
    const float* lin3_b = (const float*)d_in[17];
    float* out = (float*)d_out;

    knn_ec1_kernel<<<dim3(NN / 4, 2), 128>>>(feat0, feat1, ec1_w1, ec1_b1, ec1_w2, ec1_b2);
    ec2_kernel<<<dim3(NN / 4, 2), 128>>>(feat0, feat1, ec2_w1, ec2_b1, ec2_w2, ec2_b2);
    ab_kernel<<<dim3(NN / 4, 2), 128>>>(lin1_w, lin1_b, bn_g, bn_b);
    pair_kernel<<<dim3(TILES_PER_G, 2), 256>>>(lin2_w, lin2_b, lin3_w, lin3_b, out);
}